// round 16
// baseline (speedup 1.0000x reference)
#include <cuda_runtime.h>
#include <cuda_bf16.h>
#include <math.h>
#include <stdint.h>

#define N_ 50000
#define D_ 256
#define E_ 250000
#define T_ 6
#define H_ 4
#define K_ 64
#define MGRID 196   // ceil(N_/256); single co-resident wave
#define PGRID 391   // pool_mma grid

// ---------------- scratch (device globals; no runtime allocation) ----------
__device__ float g_hs1[(size_t)N_ * D_];
__device__ float g_hd1[(size_t)N_ * D_];
__device__ float g_hs2[(size_t)N_ * D_];
__device__ float g_hd2[(size_t)N_ * D_];
__device__ unsigned short g_h1h[(size_t)N_ * D_];
__device__ unsigned short g_h1l[(size_t)N_ * D_];
__device__ unsigned short g_h2h[(size_t)N_ * D_];
__device__ unsigned short g_h2l[(size_t)N_ * D_];
__device__ float g_pool[(size_t)K_ * D_];
__device__ float g_esum[T_];
__device__ unsigned short g_Whi[4 * 65536];
__device__ unsigned short g_Wlo[4 * 65536];
// CSR (dst-grouped edge list), rebuilt every launch
__device__ int g_deg[N_];
__device__ int g_rowptr[N_];
__device__ int g_cursor[N_];
__device__ int g_blocksum[256];
__device__ int g_eid[E_];
// monotone counters (never reset; replay-safe)
__device__ unsigned long long g_cnt;
__device__ unsigned long long g_pcnt;

// ---------------- helpers ---------------------------------------------------
__device__ __forceinline__ void redAddV2(float* p, float a, float b) {
    asm volatile("red.global.add.v2.f32 [%0], {%1,%2};"
                 :: "l"(p), "f"(a), "f"(b) : "memory");
}

__device__ __forceinline__ uint32_t smem_u32(const void* p) {
    return (uint32_t)__cvta_generic_to_shared(p);
}

#define CP_ASYNC16(dst, src) \
    asm volatile("cp.async.cg.shared.global [%0], [%1], 16;" :: "r"(dst), "l"(src))
#define CP_ASYNC16_Z(dst, src, n) \
    asm volatile("cp.async.cg.shared.global [%0], [%1], 16, %2;" :: "r"(dst), "l"(src), "r"(n))
#define CP_COMMIT() asm volatile("cp.async.commit_group;" ::: "memory")
#define CP_WAIT_ALL() asm volatile("cp.async.wait_group 0;" ::: "memory")
#define CP_WAIT_1() asm volatile("cp.async.wait_group 1;" ::: "memory")

#define STSV2(addr, r0, r1) \
    asm volatile("st.shared.v2.b32 [%0], {%1,%2};" :: "r"(addr), "r"(r0), "r"(r1) : "memory")

#define LDSM4(R0, R1, R2, R3, ADDR) \
    asm volatile("ldmatrix.sync.aligned.m8n8.x4.shared.b16 {%0,%1,%2,%3}, [%4];" \
                 : "=r"(R0), "=r"(R1), "=r"(R2), "=r"(R3) : "r"(ADDR))

#define LDSM4T(R0, R1, R2, R3, ADDR) \
    asm volatile("ldmatrix.sync.aligned.m8n8.x4.trans.shared.b16 {%0,%1,%2,%3}, [%4];" \
                 : "=r"(R0), "=r"(R1), "=r"(R2), "=r"(R3) : "r"(ADDR))

__device__ __forceinline__ void mma_bf16(float* c, const uint32_t* a, const uint32_t* b) {
    asm volatile("mma.sync.aligned.m16n8k16.row.col.f32.bf16.bf16.f32 "
                 "{%0,%1,%2,%3},{%4,%5,%6,%7},{%8,%9},{%0,%1,%2,%3};"
                 : "+f"(c[0]), "+f"(c[1]), "+f"(c[2]), "+f"(c[3])
                 : "r"(a[0]), "r"(a[1]), "r"(a[2]), "r"(a[3]), "r"(b[0]), "r"(b[1]));
}

__device__ __forceinline__ void split1(float x, unsigned short* hi, unsigned short* lo) {
    __nv_bfloat16 h = __float2bfloat16(x);
    *hi = __bfloat16_as_ushort(h);
    float r = x - __bfloat162float(h);
    *lo = __bfloat16_as_ushort(__float2bfloat16(r));
}

__device__ __forceinline__ uint32_t pack_bf2(float a, float b) {
    __nv_bfloat16 ha = __float2bfloat16(a);
    __nv_bfloat16 hb = __float2bfloat16(b);
    return (uint32_t)__bfloat16_as_ushort(ha) | ((uint32_t)__bfloat16_as_ushort(hb) << 16);
}
__device__ __forceinline__ uint32_t pack_bf2_lo(float a, float b) {
    __nv_bfloat16 ha = __float2bfloat16(a);
    __nv_bfloat16 hb = __float2bfloat16(b);
    float ra = a - __bfloat162float(ha);
    float rb = b - __bfloat162float(hb);
    return (uint32_t)__bfloat16_as_ushort(__float2bfloat16(ra)) |
           ((uint32_t)__bfloat16_as_ushort(__float2bfloat16(rb)) << 16);
}

// ---------------- grid barrier (monotone counter; no reset needed) -----------
__device__ __forceinline__ void gbar() {
    __syncthreads();
    __threadfence();
    if (threadIdx.x == 0) {
        unsigned long long old = atomicAdd(&g_cnt, 1ULL);
        unsigned long long target = (old / MGRID + 1ULL) * MGRID;
        while (atomicAdd(&g_cnt, 0ULL) < target)
            __nanosleep(64);
    }
    __syncthreads();
}

// ====== mega prologue: init + weight split + edge sums + CSR build (1 launch)
// Cross-block-mutated data read after a gbar uses __ldcg (per-SM L1 incoherent).
__global__ void __launch_bounds__(256)
mega_prep_kernel(const int* __restrict__ dst, const float* __restrict__ ea,
                 const float* __restrict__ W0, const float* __restrict__ W1,
                 const float* __restrict__ W2, const float* __restrict__ W3)
{
    const int tid = blockIdx.x * 256 + threadIdx.x;
    const int gsz = MGRID * 256;

    // P0: zero buffers + pre-split weight matrices
    for (int j = tid; j < N_; j += gsz) g_deg[j] = 0;
    for (int j = tid; j < K_ * D_; j += gsz) g_pool[j] = 0.0f;
    if (tid < T_) g_esum[tid] = 0.0f;
    for (int j = tid; j < 65536; j += gsz) {
        split1(W0[j], &g_Whi[0 * 65536 + j], &g_Wlo[0 * 65536 + j]);
        split1(W1[j], &g_Whi[1 * 65536 + j], &g_Wlo[1 * 65536 + j]);
        split1(W2[j], &g_Whi[2 * 65536 + j], &g_Wlo[2 * 65536 + j]);
        split1(W3[j], &g_Whi[3 * 65536 + j], &g_Wlo[3 * 65536 + j]);
    }
    gbar();

    // P1: degree histogram + edge_attr mean numerators
    for (int e = tid; e < E_; e += gsz) atomicAdd(&g_deg[dst[e]], 1);
    {
        int lane = threadIdx.x & 31;
#pragma unroll
        for (int t = 0; t < T_; t++) {
            float s = 0.0f;
            const float* p = ea + (size_t)t * E_;
            for (int i = tid; i < E_; i += gsz) s += p[i];
#pragma unroll
            for (int o = 16; o; o >>= 1) s += __shfl_xor_sync(0xffffffffu, s, o);
            if (lane == 0) atomicAdd(&g_esum[t], s);
        }
    }
    gbar();

    // P2: block-local exclusive scan of degrees (L1-bypass: atomics landed in L2)
    {
        __shared__ int sm[256];
        int t = threadIdx.x;
        int i = blockIdx.x * 256 + t;
        int v = (i < N_) ? __ldcg(&g_deg[i]) : 0;
        sm[t] = v;
        __syncthreads();
#pragma unroll
        for (int off = 1; off < 256; off <<= 1) {
            int x = (t >= off) ? sm[t - off] : 0;
            __syncthreads();
            sm[t] += x;
            __syncthreads();
        }
        if (i < N_) g_rowptr[i] = sm[t] - v;
        if (t == 255) g_blocksum[blockIdx.x] = sm[255];
    }
    gbar();

    // P3+P4 fused: parallel block-prefix (256-thread smem reduce over blocksums
    // below our bid), add to row range, init cursors.
    {
        __shared__ int sred[256];
        int t = threadIdx.x;
        sred[t] = (t < blockIdx.x) ? __ldcg(&g_blocksum[t]) : 0;  // MGRID < 256
        __syncthreads();
#pragma unroll
        for (int off = 128; off; off >>= 1) {
            if (t < off) sred[t] += sred[t + off];
            __syncthreads();
        }
        int s_off = sred[0];
        int i = blockIdx.x * 256 + t;
        if (i < N_) {
            int r = g_rowptr[i] + s_off;
            g_rowptr[i] = r;
            g_cursor[i] = r;
        }
    }
    gbar();

    // P5: scatter edge ids
    for (int e = tid; e < E_; e += gsz) {
        int pos = atomicAdd(&g_cursor[dst[e]], 1);
        g_eid[pos] = e;
    }
}

// =============== GEMM body (f32 A): C = f(A) @ B,  templated transform =======
// MODE 0: f = A * nm[row];  MODE 1: f = relu(A)
#define GEMM_SMEM 88064

template <int MODE>
__device__ __forceinline__ void gemm_body(
    char* dsm, const float* __restrict__ A, const float* __restrict__ nm,
    const unsigned short* __restrict__ Bhi, const unsigned short* __restrict__ Blo,
    float* __restrict__ C, int M)
{
    float* sAf = (float*)dsm;                                   // [2][4096]
    unsigned short* sBh = (unsigned short*)(dsm + 32768);       // [2][4352]
    unsigned short* sBl = (unsigned short*)(dsm + 50176);       // [2][4352]
    unsigned short* sAhi = (unsigned short*)(dsm + 67584);      // [5120]
    unsigned short* sAlo = (unsigned short*)(dsm + 77824);      // [5120]

    constexpr int ASTR = 40;
    constexpr int BSTR = 136;
    const int tid = threadIdx.x;
    const int lane = tid & 31;
    const int warp = tid >> 5;
    const int wm = (warp & 1) * 64;
    const int wn = (warp >> 1) * 32;
    const int bm = blockIdx.x * 128;
    const int bn = blockIdx.y * 128;

    float acc[4][4][4];
#pragma unroll
    for (int i = 0; i < 4; i++)
#pragma unroll
        for (int j = 0; j < 4; j++)
#pragma unroll
            for (int r = 0; r < 4; r++) acc[i][j][r] = 0.0f;

    const int arow8 = tid >> 3;
    const int acol = (tid & 7) << 2;
    float nmv[4];
    if (MODE == 0) {
#pragma unroll
        for (int rr = 0; rr < 4; rr++) {
            int grow = bm + arow8 + rr * 32;
            nmv[rr] = (grow < M) ? nm[grow] : 0.0f;
        }
    }

    auto issueA = [&](int kc, int b) {
        int k0 = kc * 32;
#pragma unroll
        for (int j = 0; j < 4; j++) {
            int idx = tid + j * 256;
            int r = idx >> 3;
            int c4 = (idx & 7) << 2;
            uint32_t dst = smem_u32(sAf + b * 4096 + r * 32 + c4);
            const float* src = A + (size_t)(bm + r) * 256 + k0 + c4;
            int n = (bm + r < M) ? 16 : 0;
            CP_ASYNC16_Z(dst, src, n);
        }
    };
    auto issueB = [&](int kc, int b) {
        int k0 = kc * 32;
#pragma unroll
        for (int j = 0; j < 2; j++) {
            int idx = tid + j * 256;
            int r = idx >> 4;
            int c8 = (idx & 15) << 3;
            CP_ASYNC16(smem_u32(sBh + b * 4352 + r * BSTR + c8),
                       Bhi + (size_t)(k0 + r) * 256 + bn + c8);
            CP_ASYNC16(smem_u32(sBl + b * 4352 + r * BSTR + c8),
                       Blo + (size_t)(k0 + r) * 256 + bn + c8);
        }
    };

    issueA(0, 0); issueB(0, 0); CP_COMMIT();

#pragma unroll 1
    for (int kc = 0; kc < 8; kc++) {
        const int b = kc & 1;
        CP_WAIT_ALL();
        __syncthreads();
        if (kc < 7) { issueA(kc + 1, b ^ 1); issueB(kc + 1, b ^ 1); CP_COMMIT(); }

#pragma unroll
        for (int rr = 0; rr < 4; rr++) {
            int r = arow8 + rr * 32;
            float4 v = *(const float4*)(sAf + b * 4096 + r * 32 + acol);
            if (MODE == 0) {
                float s = nmv[rr];
                v.x *= s; v.y *= s; v.z *= s; v.w *= s;
            } else {
                v.x = fmaxf(v.x, 0.f); v.y = fmaxf(v.y, 0.f);
                v.z = fmaxf(v.z, 0.f); v.w = fmaxf(v.w, 0.f);
            }
            int base = r * ASTR + acol;
            uint32_t h01 = pack_bf2(v.x, v.y), h23 = pack_bf2(v.z, v.w);
            uint32_t l01 = pack_bf2_lo(v.x, v.y), l23 = pack_bf2_lo(v.z, v.w);
            STSV2(smem_u32(&sAhi[base]), h01, h23);
            STSV2(smem_u32(&sAlo[base]), l01, l23);
        }
        __syncthreads();

        const unsigned short* bh_base = sBh + b * 4352;
        const unsigned short* bl_base = sBl + b * 4352;
#pragma unroll
        for (int kk = 0; kk < 32; kk += 16) {
            uint32_t ah[4][4], al[4][4], bh[4][2], bl[4][2];
            const int ar = (lane & 7) + ((lane >> 3) & 1) * 8;
            const int ac = kk + (lane >> 4) * 8;
#pragma unroll
            for (int ms = 0; ms < 4; ms++) {
                int r = wm + ms * 16 + ar;
                LDSM4(ah[ms][0], ah[ms][1], ah[ms][2], ah[ms][3],
                      smem_u32(&sAhi[r * ASTR + ac]));
                LDSM4(al[ms][0], al[ms][1], al[ms][2], al[ms][3],
                      smem_u32(&sAlo[r * ASTR + ac]));
            }
            const int brow = kk + (lane & 7) + ((lane >> 3) & 1) * 8;
#pragma unroll
            for (int g = 0; g < 2; g++) {
                int c = wn + g * 16 + (lane >> 4) * 8;
                uint32_t r0, r1, r2, r3;
                LDSM4T(r0, r1, r2, r3, smem_u32(&bh_base[brow * BSTR + c]));
                bh[g * 2][0] = r0; bh[g * 2][1] = r1;
                bh[g * 2 + 1][0] = r2; bh[g * 2 + 1][1] = r3;
                LDSM4T(r0, r1, r2, r3, smem_u32(&bl_base[brow * BSTR + c]));
                bl[g * 2][0] = r0; bl[g * 2][1] = r1;
                bl[g * 2 + 1][0] = r2; bl[g * 2 + 1][1] = r3;
            }
#pragma unroll
            for (int ms = 0; ms < 4; ms++)
#pragma unroll
                for (int ns = 0; ns < 4; ns++) {
                    mma_bf16(acc[ms][ns], ah[ms], bh[ns]);
                    mma_bf16(acc[ms][ns], ah[ms], bl[ns]);
                    mma_bf16(acc[ms][ns], al[ms], bh[ns]);
                }
        }
    }

#pragma unroll
    for (int ms = 0; ms < 4; ms++) {
#pragma unroll
        for (int ns = 0; ns < 4; ns++) {
            int row = bm + wm + ms * 16 + (lane >> 2);
            int col = bn + wn + ns * 8 + (lane & 3) * 2;
            if (row < M) {
                float2 o = make_float2(acc[ms][ns][0], acc[ms][ns][1]);
                *(float2*)(C + (size_t)row * 256 + col) = o;
            }
            if (row + 8 < M) {
                float2 o = make_float2(acc[ms][ns][2], acc[ms][ns][3]);
                *(float2*)(C + (size_t)(row + 8) * 256 + col) = o;
            }
        }
    }
}

// ---- merged 3-projection launch: z picks fully-specialized body --------------
__global__ void __launch_bounds__(256, 2)
gemm3_mma(const float* __restrict__ A0, const float* __restrict__ A1,
          const float* __restrict__ A2, const float* __restrict__ nm,
          const unsigned short* __restrict__ Wh, const unsigned short* __restrict__ Wl,
          float* __restrict__ C0, float* __restrict__ C1, float* __restrict__ C2)
{
    extern __shared__ __align__(16) char dsm[];
    if (blockIdx.z == 0)
        gemm_body<0>(dsm, A0, nm, Wh + 0 * 65536, Wl + 0 * 65536, C0, N_);
    else if (blockIdx.z == 1)
        gemm_body<0>(dsm, A1, nm, Wh + 1 * 65536, Wl + 1 * 65536, C1, N_);
    else
        gemm_body<1>(dsm, A2, nm, Wh + 2 * 65536, Wl + 2 * 65536, C2, N_);
}

// ====== GEMM (pre-split A): all operands staged by raw cp.async, no split ====
#define GEMMP_SMEM 75776

__global__ void __launch_bounds__(256, 2)
gemm_pre(const unsigned short* __restrict__ Ah, const unsigned short* __restrict__ Al,
         const unsigned short* __restrict__ Bhi, const unsigned short* __restrict__ Blo,
         float* __restrict__ C, int M)
{
    extern __shared__ __align__(16) char dsm[];
    unsigned short* sAh = (unsigned short*)dsm;                  // [2][5120]
    unsigned short* sAl = (unsigned short*)(dsm + 20480);        // [2][5120]
    unsigned short* sBh = (unsigned short*)(dsm + 40960);        // [2][4352]
    unsigned short* sBl = (unsigned short*)(dsm + 58368);        // [2][4352]

    constexpr int ASTR = 40;
    constexpr int BSTR = 136;
    const int tid = threadIdx.x;
    const int lane = tid & 31;
    const int warp = tid >> 5;
    const int wm = (warp & 1) * 64;
    const int wn = (warp >> 1) * 32;
    const int bm = blockIdx.x * 128;
    const int bn = blockIdx.y * 128;

    float acc[4][4][4];
#pragma unroll
    for (int i = 0; i < 4; i++)
#pragma unroll
        for (int j = 0; j < 4; j++)
#pragma unroll
            for (int r = 0; r < 4; r++) acc[i][j][r] = 0.0f;

    auto issue = [&](int kc, int b) {
        int k0 = kc * 32;
#pragma unroll
        for (int j = 0; j < 2; j++) {
            int idx = tid + j * 256;
            int r = idx >> 2;
            int c8 = (idx & 3) << 3;
            int n = (bm + r < M) ? 16 : 0;
            CP_ASYNC16_Z(smem_u32(&sAh[b * 5120 + r * ASTR + c8]),
                         Ah + (size_t)(bm + r) * 256 + k0 + c8, n);
            CP_ASYNC16_Z(smem_u32(&sAl[b * 5120 + r * ASTR + c8]),
                         Al + (size_t)(bm + r) * 256 + k0 + c8, n);
            int rb = idx >> 4;
            int cb = (idx & 15) << 3;
            CP_ASYNC16(smem_u32(&sBh[b * 4352 + rb * BSTR + cb]),
                       Bhi + (size_t)(k0 + rb) * 256 + bn + cb);
            CP_ASYNC16(smem_u32(&sBl[b * 4352 + rb * BSTR + cb]),
                       Blo + (size_t)(k0 + rb) * 256 + bn + cb);
        }
        CP_COMMIT();
    };

    issue(0, 0);
    issue(1, 1);

#pragma unroll 1
    for (int kc = 0; kc < 8; kc++) {
        const int b = kc & 1;
        if (kc < 6) { CP_WAIT_1(); } else { CP_WAIT_ALL(); }
        __syncthreads();

        const unsigned short* ah_base = sAh + b * 5120;
        const unsigned short* al_base = sAl + b * 5120;
        const unsigned short* bh_base = sBh + b * 4352;
        const unsigned short* bl_base = sBl + b * 4352;
#pragma unroll
        for (int kk = 0; kk < 32; kk += 16) {
            uint32_t ah[4][4], al[4][4], bh[4][2], bl[4][2];
            const int ar = (lane & 7) + ((lane >> 3) & 1) * 8;
            const int ac = kk + (lane >> 4) * 8;
#pragma unroll
            for (int ms = 0; ms < 4; ms++) {
                int r = wm + ms * 16 + ar;
                LDSM4(ah[ms][0], ah[ms][1], ah[ms][2], ah[ms][3],
                      smem_u32(&ah_base[r * ASTR + ac]));
                LDSM4(al[ms][0], al[ms][1], al[ms][2], al[ms][3],
                      smem_u32(&al_base[r * ASTR + ac]));
            }
            const int brow = kk + (lane & 7) + ((lane >> 3) & 1) * 8;
#pragma unroll
            for (int g = 0; g < 2; g++) {
                int c = wn + g * 16 + (lane >> 4) * 8;
                uint32_t r0, r1, r2, r3;
                LDSM4T(r0, r1, r2, r3, smem_u32(&bh_base[brow * BSTR + c]));
                bh[g * 2][0] = r0; bh[g * 2][1] = r1;
                bh[g * 2 + 1][0] = r2; bh[g * 2 + 1][1] = r3;
                LDSM4T(r0, r1, r2, r3, smem_u32(&bl_base[brow * BSTR + c]));
                bl[g * 2][0] = r0; bl[g * 2][1] = r1;
                bl[g * 2 + 1][0] = r2; bl[g * 2 + 1][1] = r3;
            }
#pragma unroll
            for (int ms = 0; ms < 4; ms++)
#pragma unroll
                for (int ns = 0; ns < 4; ns++) {
                    mma_bf16(acc[ms][ns], ah[ms], bh[ns]);
                    mma_bf16(acc[ms][ns], ah[ms], bl[ns]);
                    mma_bf16(acc[ms][ns], al[ms], bh[ns]);
                }
        }
        __syncthreads();
        if (kc < 6) issue(kc + 2, b);
    }

#pragma unroll
    for (int ms = 0; ms < 4; ms++) {
#pragma unroll
        for (int ns = 0; ns < 4; ns++) {
            int row = bm + wm + ms * 16 + (lane >> 2);
            int col = bn + wn + ns * 8 + (lane & 3) * 2;
            if (row < M) {
                float2 o = make_float2(acc[ms][ns][0], acc[ms][ns][1]);
                *(float2*)(C + (size_t)row * 256 + col) = o;
            }
            if (row + 8 < M) {
                float2 o = make_float2(acc[ms][ns][2], acc[ms][ns][3]);
                *(float2*)(C + (size_t)(row + 8) * 256 + col) = o;
            }
        }
    }
}

// ---------- warp-per-node fused GAT; writes PRE-SPLIT bf16 hi/lo --------------
template <int RELU>
__global__ void __launch_bounds__(256)
node_gat_kernel(const int* __restrict__ src, const float* __restrict__ emask,
                const float* __restrict__ hs, const float* __restrict__ hd,
                const float* __restrict__ a,
                unsigned short* __restrict__ hh, unsigned short* __restrict__ hl)
{
    int n = (blockIdx.x * blockDim.x + threadIdx.x) >> 5;
    int lane = threadIdx.x & 31;
    if (n >= N_) return;

    const float4* hdp = (const float4*)(hd + (size_t)n * 256) + lane * 2;
    float4 d0 = __ldg(hdp), d1 = __ldg(hdp + 1);
    const float4* ap = (const float4*)a + lane * 2;
    float4 a0 = __ldg(ap), a1v = __ldg(ap + 1);

    float acc[8];
#pragma unroll
    for (int i = 0; i < 8; i++) acc[i] = 0.0f;
    float den = 0.0f;

    int beg = __ldg(&g_rowptr[n]);
    int end = __ldg(&g_cursor[n]);

    float4 n0, n1;
    float emN = 0.0f;
    if (beg < end) {
        int e = __ldg(&g_eid[beg]);
        int s = __ldg(&src[e]);
        emN = __ldg(&emask[e]);
        const float4* hsp = (const float4*)(hs + (size_t)s * 256) + lane * 2;
        n0 = __ldg(hsp); n1 = __ldg(hsp + 1);
    }

    for (int i = beg; i < end; i++) {
        float4 s0 = n0, s1 = n1;
        float em = emN;
        if (i + 1 < end) {
            int e = __ldg(&g_eid[i + 1]);
            int s = __ldg(&src[e]);
            emN = __ldg(&emask[e]);
            const float4* hsp = (const float4*)(hs + (size_t)s * 256) + lane * 2;
            n0 = __ldg(hsp); n1 = __ldg(hsp + 1);
        }

        float v, part = 0.0f;
        v = s0.x + d0.x; v = v > 0.f ? v : 0.2f * v; part = fmaf(a0.x, v, part);
        v = s0.y + d0.y; v = v > 0.f ? v : 0.2f * v; part = fmaf(a0.y, v, part);
        v = s0.z + d0.z; v = v > 0.f ? v : 0.2f * v; part = fmaf(a0.z, v, part);
        v = s0.w + d0.w; v = v > 0.f ? v : 0.2f * v; part = fmaf(a0.w, v, part);
        v = s1.x + d1.x; v = v > 0.f ? v : 0.2f * v; part = fmaf(a1v.x, v, part);
        v = s1.y + d1.y; v = v > 0.f ? v : 0.2f * v; part = fmaf(a1v.y, v, part);
        v = s1.z + d1.z; v = v > 0.f ? v : 0.2f * v; part = fmaf(a1v.z, v, part);
        v = s1.w + d1.w; v = v > 0.f ? v : 0.2f * v; part = fmaf(a1v.w, v, part);

        part += __shfl_xor_sync(0xffffffffu, part, 1);
        part += __shfl_xor_sync(0xffffffffu, part, 2);
        part += __shfl_xor_sync(0xffffffffu, part, 4);

        float p = expf(part);
        den += p;
        float w = p * em;
        acc[0] = fmaf(w, s0.x, acc[0]); acc[1] = fmaf(w, s0.y, acc[1]);
        acc[2] = fmaf(w, s0.z, acc[2]); acc[3] = fmaf(w, s0.w, acc[3]);
        acc[4] = fmaf(w, s1.x, acc[4]); acc[5] = fmaf(w, s1.y, acc[5]);
        acc[6] = fmaf(w, s1.z, acc[6]); acc[7] = fmaf(w, s1.w, acc[7]);
    }

    float inv = 1.0f / (den + 1e-16f);
#pragma unroll
    for (int i = 0; i < 8; i++) {
        acc[i] *= inv;
        if (RELU) acc[i] = fmaxf(acc[i], 0.0f);
    }
    size_t off = (size_t)n * 256 + lane * 8;
    uint4 oh, ol;
    oh.x = pack_bf2(acc[0], acc[1]); oh.y = pack_bf2(acc[2], acc[3]);
    oh.z = pack_bf2(acc[4], acc[5]); oh.w = pack_bf2(acc[6], acc[7]);
    ol.x = pack_bf2_lo(acc[0], acc[1]); ol.y = pack_bf2_lo(acc[2], acc[3]);
    ol.z = pack_bf2_lo(acc[4], acc[5]); ol.w = pack_bf2_lo(acc[6], acc[7]);
    *(uint4*)(hh + off) = oh;
    *(uint4*)(hl + off) = ol;
}

// ----- MMA pool (+fused final classifier in the last block to finish) --------
#define XSTR 264
#define WSTR 72
#define POOL_SMEM (2 * 128 * XSTR * 2 + 2 * 256 * WSTR * 2)

__global__ void __launch_bounds__(256)
pool_mma(const unsigned short* __restrict__ Xhg, const unsigned short* __restrict__ Xlg,
         const float* __restrict__ Wa, const float* __restrict__ Wcls,
         const float* __restrict__ bcls, float* __restrict__ out)
{
    extern __shared__ __align__(16) char smem[];
    unsigned short* Xh = (unsigned short*)smem;
    unsigned short* Xl = Xh + 128 * XSTR;
    unsigned short* Wh = Xl + 128 * XSTR;
    unsigned short* Wl = Wh + 256 * WSTR;
    unsigned short* Sh = Wh;
    unsigned short* Sl = Wl;

    const int tid = threadIdx.x;
    const int lane = tid & 31;
    const int warp = tid >> 5;
    const int row0 = blockIdx.x * 128;

#pragma unroll
    for (int j = 0; j < 16; j++) {
        int idx = tid + j * 256;
        int r = idx >> 5;
        int c8 = (idx & 31) << 3;
        int grow = row0 + r;
        int n = (grow < N_) ? 16 : 0;
        CP_ASYNC16_Z(smem_u32(&Xh[r * XSTR + c8]), Xhg + (size_t)grow * 256 + c8, n);
        CP_ASYNC16_Z(smem_u32(&Xl[r * XSTR + c8]), Xlg + (size_t)grow * 256 + c8, n);
    }
    CP_COMMIT();
#pragma unroll
    for (int j = 0; j < 16; j++) {
        int idx = tid + j * 256;
        int r = idx >> 4;
        int c4 = (idx & 15) << 2;
        float4 v = *(const float4*)(Wa + (size_t)r * 64 + c4);
        int base = r * WSTR + c4;
        uint32_t h01 = pack_bf2(v.x, v.y), h23 = pack_bf2(v.z, v.w);
        uint32_t l01 = pack_bf2_lo(v.x, v.y), l23 = pack_bf2_lo(v.z, v.w);
        STSV2(smem_u32(&Wh[base]), h01, h23);
        STSV2(smem_u32(&Wl[base]), l01, l23);
    }
    CP_WAIT_ALL();
    __syncthreads();

    float sc[8][4];
#pragma unroll
    for (int i = 0; i < 8; i++)
#pragma unroll
        for (int r = 0; r < 4; r++) sc[i][r] = 0.0f;

    const int arow = (lane & 7) + ((lane >> 3) & 1) * 8;
#pragma unroll 1
    for (int k = 0; k < 256; k += 16) {
        uint32_t ah[4], al[4];
        int rbase = (warp * 16 + arow) * XSTR + k + (lane >> 4) * 8;
        LDSM4(ah[0], ah[1], ah[2], ah[3], smem_u32(&Xh[rbase]));
        LDSM4(al[0], al[1], al[2], al[3], smem_u32(&Xl[rbase]));
        uint32_t bh[8][2], bl[8][2];
        int brow = k + (lane & 7) + ((lane >> 3) & 1) * 8;
#pragma unroll
        for (int g = 0; g < 4; g++) {
            int c = g * 16 + (lane >> 4) * 8;
            uint32_t r0, r1, r2, r3;
            LDSM4T(r0, r1, r2, r3, smem_u32(&Wh[brow * WSTR + c]));
            bh[g * 2][0] = r0; bh[g * 2][1] = r1;
            bh[g * 2 + 1][0] = r2; bh[g * 2 + 1][1] = r3;
            LDSM4T(r0, r1, r2, r3, smem_u32(&Wl[brow * WSTR + c]));
            bl[g * 2][0] = r0; bl[g * 2][1] = r1;
            bl[g * 2 + 1][0] = r2; bl[g * 2 + 1][1] = r3;
        }
#pragma unroll
        for (int ns = 0; ns < 8; ns++) {
            mma_bf16(sc[ns], ah, bh[ns]);
            mma_bf16(sc[ns], ah, bl[ns]);
            mma_bf16(sc[ns], al, bh[ns]);
        }
    }

    float mA = -1e30f, mB = -1e30f;
#pragma unroll
    for (int ns = 0; ns < 8; ns++) {
        mA = fmaxf(mA, fmaxf(sc[ns][0], sc[ns][1]));
        mB = fmaxf(mB, fmaxf(sc[ns][2], sc[ns][3]));
    }
    mA = fmaxf(mA, __shfl_xor_sync(0xffffffffu, mA, 1));
    mA = fmaxf(mA, __shfl_xor_sync(0xffffffffu, mA, 2));
    mB = fmaxf(mB, __shfl_xor_sync(0xffffffffu, mB, 1));
    mB = fmaxf(mB, __shfl_xor_sync(0xffffffffu, mB, 2));
    float sumA = 0.0f, sumB = 0.0f;
#pragma unroll
    for (int ns = 0; ns < 8; ns++) {
        sc[ns][0] = expf(sc[ns][0] - mA); sc[ns][1] = expf(sc[ns][1] - mA);
        sc[ns][2] = expf(sc[ns][2] - mB); sc[ns][3] = expf(sc[ns][3] - mB);
        sumA += sc[ns][0] + sc[ns][1];
        sumB += sc[ns][2] + sc[ns][3];
    }
    sumA += __shfl_xor_sync(0xffffffffu, sumA, 1);
    sumA += __shfl_xor_sync(0xffffffffu, sumA, 2);
    sumB += __shfl_xor_sync(0xffffffffu, sumB, 1);
    sumB += __shfl_xor_sync(0xffffffffu, sumB, 2);
    float invA = 1.0f / sumA, invB = 1.0f / sumB;

    __syncthreads();

    {
        int rA = warp * 16 + (lane >> 2);
        int rB = rA + 8;
        int colb = (lane & 3) * 2;
#pragma unroll
        for (int ns = 0; ns < 8; ns++) {
            int col = ns * 8 + colb;
            float a0 = sc[ns][0] * invA, a1 = sc[ns][1] * invA;
            float b0 = sc[ns][2] * invB, b1 = sc[ns][3] * invB;
            *(uint32_t*)&Sh[rA * WSTR + col] = pack_bf2(a0, a1);
            *(uint32_t*)&Sl[rA * WSTR + col] = pack_bf2_lo(a0, a1);
            *(uint32_t*)&Sh[rB * WSTR + col] = pack_bf2(b0, b1);
            *(uint32_t*)&Sl[rB * WSTR + col] = pack_bf2_lo(b0, b1);
        }
    }
    __syncthreads();

    float pc[4][4][4];
#pragma unroll
    for (int i = 0; i < 4; i++)
#pragma unroll
        for (int j = 0; j < 4; j++)
#pragma unroll
            for (int r = 0; r < 4; r++) pc[i][j][r] = 0.0f;

    const int nw = warp * 32;
#pragma unroll 1
    for (int kk = 0; kk < 128; kk += 16) {
        uint32_t sah[4][4], sal[4][4];
        int srow = kk + ((lane >> 4) & 1) * 8 + (lane & 7);
        int scoff = ((lane >> 3) & 1) * 8;
#pragma unroll
        for (int mt = 0; mt < 4; mt++) {
            int sc2 = mt * 16 + scoff;
            LDSM4T(sah[mt][0], sah[mt][1], sah[mt][2], sah[mt][3],
                   smem_u32(&Sh[srow * WSTR + sc2]));
            LDSM4T(sal[mt][0], sal[mt][1], sal[mt][2], sal[mt][3],
                   smem_u32(&Sl[srow * WSTR + sc2]));
        }
        uint32_t xbh[4][2], xbl[4][2];
        int brow = kk + (lane & 7) + ((lane >> 3) & 1) * 8;
#pragma unroll
        for (int g = 0; g < 2; g++) {
            int c = nw + g * 16 + (lane >> 4) * 8;
            uint32_t r0, r1, r2, r3;
            LDSM4T(r0, r1, r2, r3, smem_u32(&Xh[brow * XSTR + c]));
            xbh[g * 2][0] = r0; xbh[g * 2][1] = r1;
            xbh[g * 2 + 1][0] = r2; xbh[g * 2 + 1][1] = r3;
            LDSM4T(r0, r1, r2, r3, smem_u32(&Xl[brow * XSTR + c]));
            xbl[g * 2][0] = r0; xbl[g * 2][1] = r1;
            xbl[g * 2 + 1][0] = r2; xbl[g * 2 + 1][1] = r3;
        }
#pragma unroll
        for (int mt = 0; mt < 4; mt++)
#pragma unroll
            for (int ns = 0; ns < 4; ns++) {
                mma_bf16(pc[mt][ns], sah[mt], xbh[ns]);
                mma_bf16(pc[mt][ns], sah[mt], xbl[ns]);
                mma_bf16(pc[mt][ns], sal[mt], xbh[ns]);
            }
    }

#pragma unroll
    for (int mt = 0; mt < 4; mt++)
#pragma unroll
        for (int ns = 0; ns < 4; ns++) {
            int kidx = mt * 16 + (lane >> 2);
            int col = nw + ns * 8 + (lane & 3) * 2;
            redAddV2(&g_pool[(size_t)kidx * 256 + col], pc[mt][ns][0], pc[mt][ns][1]);
            redAddV2(&g_pool[(size_t)(kidx + 8) * 256 + col], pc[mt][ns][2], pc[mt][ns][3]);
        }

    // ---- fused final classifier: last block to finish does it -------------
    __threadfence();
    __shared__ unsigned int s_last;
    if (tid == 0) {
        unsigned long long old = atomicAdd(&g_pcnt, 1ULL);
        s_last = ((old % (unsigned long long)PGRID) == (unsigned long long)(PGRID - 1));
    }
    __syncthreads();
    if (s_last) {
        // 8 warps, each handles rows warp, warp+8, ... (K_=64)
        for (int k = warp; k < K_; k += 8) {
            float s = 0.0f;
            for (int d = lane; d < 256; d += 32)
                s += __ldcg(&g_pool[(size_t)k * 256 + d]) * Wcls[d];
#pragma unroll
            for (int o = 16; o; o >>= 1) s += __shfl_xor_sync(0xffffffffu, s, o);
            if (lane == 0) {
                float extra = 0.0f;
#pragma unroll
                for (int t = 0; t < T_; t++)
                    extra += (g_esum[t] * (1.0f / E_)) * Wcls[256 + t];
                float z = s + extra + bcls[0];
                out[k] = 1.0f / (1.0f + expf(-z));
            }
        }
    }
}

// ---------------- launch -------------------------------------------------------
extern "C" void kernel_launch(void* const* d_in, const int* in_sizes, int n_in,
                              void* d_out, int out_size)
{
    const float* x_pkg = (const float*)d_in[0];
    const float* x_dst = (const float*)d_in[1];
    const int*   eidx  = (const int*)d_in[2];
    const float* eattr = (const float*)d_in[3];
    const float* nmask = (const float*)d_in[4];
    const float* emask = (const float*)d_in[5];
    const float* W1s   = (const float*)d_in[6];
    const float* W1d   = (const float*)d_in[7];
    const float* a1    = (const float*)d_in[8];
    const float* W2s   = (const float*)d_in[9];
    const float* W2d   = (const float*)d_in[10];
    const float* a2    = (const float*)d_in[11];
    const float* Was   = (const float*)d_in[12];
    const float* Wcl   = (const float*)d_in[13];
    const float* bcl   = (const float*)d_in[14];
    float* out = (float*)d_out;

    const int tsel = T_ - 1;
    const int* src5 = eidx + (size_t)tsel * 2 * E_;
    const int* dst5 = src5 + E_;
    const float* x_dst5 = x_dst + (size_t)tsel * N_ * D_;
    const float* W1s5 = W1s + (size_t)tsel * D_ * 256;
    const float* W1d5 = W1d + (size_t)tsel * D_ * 256;
    const float* a1_5 = a1 + (size_t)tsel * 256;
    const float* W2s5 = W2s + (size_t)tsel * D_ * 256;
    const float* W2d5 = W2d + (size_t)tsel * D_ * 256;
    const float* a2_5 = a2 + (size_t)tsel * 256;

    float *hs1, *hd1, *hs2, *hd2;
    unsigned short *whi, *wlo, *h1h, *h1l, *h2h, *h2l;
    cudaGetSymbolAddress((void**)&hs1, g_hs1);
    cudaGetSymbolAddress((void**)&hd1, g_hd1);
    cudaGetSymbolAddress((void**)&hs2, g_hs2);
    cudaGetSymbolAddress((void**)&hd2, g_hd2);
    cudaGetSymbolAddress((void**)&whi, g_Whi);
    cudaGetSymbolAddress((void**)&wlo, g_Wlo);
    cudaGetSymbolAddress((void**)&h1h, g_h1h);
    cudaGetSymbolAddress((void**)&h1l, g_h1l);
    cudaGetSymbolAddress((void**)&h2h, g_h2h);
    cudaGetSymbolAddress((void**)&h2l, g_h2l);

    cudaFuncSetAttribute(pool_mma, cudaFuncAttributeMaxDynamicSharedMemorySize, POOL_SMEM);
    cudaFuncSetAttribute(gemm3_mma, cudaFuncAttributeMaxDynamicSharedMemorySize, GEMM_SMEM);
    cudaFuncSetAttribute(gemm_pre, cudaFuncAttributeMaxDynamicSharedMemorySize, GEMMP_SMEM);

    const int ngrid = (N_ * 32 + 255) / 256;

    // ONE launch: init + weight split + edge sums + full CSR build
    mega_prep_kernel<<<MGRID, 256>>>(dst5, eattr, W1s5, W1d5, W2s5, W2d5);

    // 3 independent projections in ONE launch; per-z fully templated dispatch
    gemm3_mma<<<dim3(391, 2, 3), 256, GEMM_SMEM>>>(x_pkg, x_dst5, x_pkg, nmask,
                                                   whi, wlo, hs1, hd1, hs2);

    node_gat_kernel<1><<<ngrid, 256>>>(src5, emask, hs1, hd1, a1_5, h1h, h1l);

    gemm_pre<<<dim3(391, 2), 256, GEMMP_SMEM>>>(h1h, h1l, whi + 3 * 65536, wlo + 3 * 65536, hd2, N_);

    node_gat_kernel<0><<<ngrid, 256>>>(src5, emask, hs2, hd2, a2_5, h2h, h2l);

    // pool + fused final classifier (last block runs it)
    pool_mma<<<PGRID, 256, POOL_SMEM>>>(h2h, h2l, Was, Wcl, bcl, out);
}

// round 17
// speedup vs baseline: 1.4552x; 1.4552x over previous
#include <cuda_runtime.h>
#include <cuda_bf16.h>
#include <math.h>
#include <stdint.h>

#define N_ 50000
#define D_ 256
#define E_ 250000
#define T_ 6
#define H_ 4
#define K_ 64
#define MGRID 196   // ceil(N_/256); single co-resident wave

// ---------------- scratch (device globals; no runtime allocation) ----------
__device__ float g_hs1[(size_t)N_ * D_];
__device__ float g_hd1[(size_t)N_ * D_];
__device__ float g_hs2[(size_t)N_ * D_];
__device__ float g_hd2[(size_t)N_ * D_];
__device__ unsigned short g_h1h[(size_t)N_ * D_];
__device__ unsigned short g_h1l[(size_t)N_ * D_];
__device__ unsigned short g_h2h[(size_t)N_ * D_];
__device__ unsigned short g_h2l[(size_t)N_ * D_];
__device__ float g_pool[(size_t)K_ * D_];
__device__ float g_esum[T_];
__device__ unsigned short g_Whi[4 * 65536];
__device__ unsigned short g_Wlo[4 * 65536];
// CSR (dst-grouped edge list), rebuilt every launch
__device__ int g_deg[N_];
__device__ int g_rowptr[N_];
__device__ int g_cursor[N_];
__device__ int g_blocksum[256];
__device__ int g_eid[E_];
// monotone grid-barrier counter (never reset; replay-safe)
__device__ unsigned long long g_cnt;

// ---------------- helpers ---------------------------------------------------
__device__ __forceinline__ void redAddV2(float* p, float a, float b) {
    asm volatile("red.global.add.v2.f32 [%0], {%1,%2};"
                 :: "l"(p), "f"(a), "f"(b) : "memory");
}

__device__ __forceinline__ uint32_t smem_u32(const void* p) {
    return (uint32_t)__cvta_generic_to_shared(p);
}

#define CP_ASYNC16(dst, src) \
    asm volatile("cp.async.cg.shared.global [%0], [%1], 16;" :: "r"(dst), "l"(src))
#define CP_ASYNC16_Z(dst, src, n) \
    asm volatile("cp.async.cg.shared.global [%0], [%1], 16, %2;" :: "r"(dst), "l"(src), "r"(n))
#define CP_COMMIT() asm volatile("cp.async.commit_group;" ::: "memory")
#define CP_WAIT_ALL() asm volatile("cp.async.wait_group 0;" ::: "memory")
#define CP_WAIT_1() asm volatile("cp.async.wait_group 1;" ::: "memory")

#define STSV2(addr, r0, r1) \
    asm volatile("st.shared.v2.b32 [%0], {%1,%2};" :: "r"(addr), "r"(r0), "r"(r1) : "memory")

#define LDSM4(R0, R1, R2, R3, ADDR) \
    asm volatile("ldmatrix.sync.aligned.m8n8.x4.shared.b16 {%0,%1,%2,%3}, [%4];" \
                 : "=r"(R0), "=r"(R1), "=r"(R2), "=r"(R3) : "r"(ADDR))

#define LDSM4T(R0, R1, R2, R3, ADDR) \
    asm volatile("ldmatrix.sync.aligned.m8n8.x4.trans.shared.b16 {%0,%1,%2,%3}, [%4];" \
                 : "=r"(R0), "=r"(R1), "=r"(R2), "=r"(R3) : "r"(ADDR))

__device__ __forceinline__ void mma_bf16(float* c, const uint32_t* a, const uint32_t* b) {
    asm volatile("mma.sync.aligned.m16n8k16.row.col.f32.bf16.bf16.f32 "
                 "{%0,%1,%2,%3},{%4,%5,%6,%7},{%8,%9},{%0,%1,%2,%3};"
                 : "+f"(c[0]), "+f"(c[1]), "+f"(c[2]), "+f"(c[3])
                 : "r"(a[0]), "r"(a[1]), "r"(a[2]), "r"(a[3]), "r"(b[0]), "r"(b[1]));
}

__device__ __forceinline__ void split1(float x, unsigned short* hi, unsigned short* lo) {
    __nv_bfloat16 h = __float2bfloat16(x);
    *hi = __bfloat16_as_ushort(h);
    float r = x - __bfloat162float(h);
    *lo = __bfloat16_as_ushort(__float2bfloat16(r));
}

__device__ __forceinline__ uint32_t pack_bf2(float a, float b) {
    __nv_bfloat16 ha = __float2bfloat16(a);
    __nv_bfloat16 hb = __float2bfloat16(b);
    return (uint32_t)__bfloat16_as_ushort(ha) | ((uint32_t)__bfloat16_as_ushort(hb) << 16);
}
__device__ __forceinline__ uint32_t pack_bf2_lo(float a, float b) {
    __nv_bfloat16 ha = __float2bfloat16(a);
    __nv_bfloat16 hb = __float2bfloat16(b);
    float ra = a - __bfloat162float(ha);
    float rb = b - __bfloat162float(hb);
    return (uint32_t)__bfloat16_as_ushort(__float2bfloat16(ra)) |
           ((uint32_t)__bfloat16_as_ushort(__float2bfloat16(rb)) << 16);
}

// ---------------- grid barrier (monotone counter; no reset needed) -----------
__device__ __forceinline__ void gbar() {
    __syncthreads();
    __threadfence();
    if (threadIdx.x == 0) {
        unsigned long long old = atomicAdd(&g_cnt, 1ULL);
        unsigned long long target = (old / MGRID + 1ULL) * MGRID;
        while (atomicAdd(&g_cnt, 0ULL) < target)
            __nanosleep(64);
    }
    __syncthreads();
}

// ====== mega prologue: init + weight split + edge sums + CSR build (1 launch)
// Cross-block-mutated data read after a gbar uses __ldcg (per-SM L1 incoherent).
__global__ void __launch_bounds__(256)
mega_prep_kernel(const int* __restrict__ dst, const float* __restrict__ ea,
                 const float* __restrict__ W0, const float* __restrict__ W1,
                 const float* __restrict__ W2, const float* __restrict__ W3)
{
    const int tid = blockIdx.x * 256 + threadIdx.x;
    const int gsz = MGRID * 256;

    // P0: zero buffers + pre-split weight matrices
    for (int j = tid; j < N_; j += gsz) g_deg[j] = 0;
    for (int j = tid; j < K_ * D_; j += gsz) g_pool[j] = 0.0f;
    if (tid < T_) g_esum[tid] = 0.0f;
    for (int j = tid; j < 65536; j += gsz) {
        split1(W0[j], &g_Whi[0 * 65536 + j], &g_Wlo[0 * 65536 + j]);
        split1(W1[j], &g_Whi[1 * 65536 + j], &g_Wlo[1 * 65536 + j]);
        split1(W2[j], &g_Whi[2 * 65536 + j], &g_Wlo[2 * 65536 + j]);
        split1(W3[j], &g_Whi[3 * 65536 + j], &g_Wlo[3 * 65536 + j]);
    }
    gbar();

    // P1: degree histogram + edge_attr mean numerators
    for (int e = tid; e < E_; e += gsz) atomicAdd(&g_deg[dst[e]], 1);
    {
        int lane = threadIdx.x & 31;
#pragma unroll
        for (int t = 0; t < T_; t++) {
            float s = 0.0f;
            const float* p = ea + (size_t)t * E_;
            for (int i = tid; i < E_; i += gsz) s += p[i];
#pragma unroll
            for (int o = 16; o; o >>= 1) s += __shfl_xor_sync(0xffffffffu, s, o);
            if (lane == 0) atomicAdd(&g_esum[t], s);
        }
    }
    gbar();

    // P2: block-local exclusive scan of degrees (L1-bypass: atomics landed in L2)
    {
        __shared__ int sm[256];
        int t = threadIdx.x;
        int i = blockIdx.x * 256 + t;
        int v = (i < N_) ? __ldcg(&g_deg[i]) : 0;
        sm[t] = v;
        __syncthreads();
#pragma unroll
        for (int off = 1; off < 256; off <<= 1) {
            int x = (t >= off) ? sm[t - off] : 0;
            __syncthreads();
            sm[t] += x;
            __syncthreads();
        }
        if (i < N_) g_rowptr[i] = sm[t] - v;
        if (t == 255) g_blocksum[blockIdx.x] = sm[255];
    }
    gbar();

    // P3+P4 fused: every block computes its own prefix over blocksums (ldcg),
    // adds to its row range, inits cursors.
    {
        __shared__ int s_off;
        if (threadIdx.x == 0) {
            int pre = 0;
            for (int b = 0; b < blockIdx.x; b++) pre += __ldcg(&g_blocksum[b]);
            s_off = pre;
        }
        __syncthreads();
        int i = blockIdx.x * 256 + threadIdx.x;
        if (i < N_) {
            int r = g_rowptr[i] + s_off;
            g_rowptr[i] = r;
            g_cursor[i] = r;
        }
    }
    gbar();

    // P5: scatter edge ids
    for (int e = tid; e < E_; e += gsz) {
        int pos = atomicAdd(&g_cursor[dst[e]], 1);
        g_eid[pos] = e;
    }
}

// =============== GEMM body (f32 A): C = f(A) @ B,  templated transform =======
// MODE 0: f = A * nm[row];  MODE 1: f = relu(A)
#define GEMM_SMEM 88064

template <int MODE>
__device__ __forceinline__ void gemm_body(
    char* dsm, const float* __restrict__ A, const float* __restrict__ nm,
    const unsigned short* __restrict__ Bhi, const unsigned short* __restrict__ Blo,
    float* __restrict__ C, int M)
{
    float* sAf = (float*)dsm;                                   // [2][4096]
    unsigned short* sBh = (unsigned short*)(dsm + 32768);       // [2][4352]
    unsigned short* sBl = (unsigned short*)(dsm + 50176);       // [2][4352]
    unsigned short* sAhi = (unsigned short*)(dsm + 67584);      // [5120]
    unsigned short* sAlo = (unsigned short*)(dsm + 77824);      // [5120]

    constexpr int ASTR = 40;
    constexpr int BSTR = 136;
    const int tid = threadIdx.x;
    const int lane = tid & 31;
    const int warp = tid >> 5;
    const int wm = (warp & 1) * 64;
    const int wn = (warp >> 1) * 32;
    const int bm = blockIdx.x * 128;
    const int bn = blockIdx.y * 128;

    float acc[4][4][4];
#pragma unroll
    for (int i = 0; i < 4; i++)
#pragma unroll
        for (int j = 0; j < 4; j++)
#pragma unroll
            for (int r = 0; r < 4; r++) acc[i][j][r] = 0.0f;

    const int arow8 = tid >> 3;
    const int acol = (tid & 7) << 2;
    float nmv[4];
    if (MODE == 0) {
#pragma unroll
        for (int rr = 0; rr < 4; rr++) {
            int grow = bm + arow8 + rr * 32;
            nmv[rr] = (grow < M) ? nm[grow] : 0.0f;
        }
    }

    auto issueA = [&](int kc, int b) {
        int k0 = kc * 32;
#pragma unroll
        for (int j = 0; j < 4; j++) {
            int idx = tid + j * 256;
            int r = idx >> 3;
            int c4 = (idx & 7) << 2;
            uint32_t dst = smem_u32(sAf + b * 4096 + r * 32 + c4);
            const float* src = A + (size_t)(bm + r) * 256 + k0 + c4;
            int n = (bm + r < M) ? 16 : 0;
            CP_ASYNC16_Z(dst, src, n);
        }
    };
    auto issueB = [&](int kc, int b) {
        int k0 = kc * 32;
#pragma unroll
        for (int j = 0; j < 2; j++) {
            int idx = tid + j * 256;
            int r = idx >> 4;
            int c8 = (idx & 15) << 3;
            CP_ASYNC16(smem_u32(sBh + b * 4352 + r * BSTR + c8),
                       Bhi + (size_t)(k0 + r) * 256 + bn + c8);
            CP_ASYNC16(smem_u32(sBl + b * 4352 + r * BSTR + c8),
                       Blo + (size_t)(k0 + r) * 256 + bn + c8);
        }
    };

    issueA(0, 0); issueB(0, 0); CP_COMMIT();

#pragma unroll 1
    for (int kc = 0; kc < 8; kc++) {
        const int b = kc & 1;
        CP_WAIT_ALL();
        __syncthreads();
        if (kc < 7) { issueA(kc + 1, b ^ 1); issueB(kc + 1, b ^ 1); CP_COMMIT(); }

#pragma unroll
        for (int rr = 0; rr < 4; rr++) {
            int r = arow8 + rr * 32;
            float4 v = *(const float4*)(sAf + b * 4096 + r * 32 + acol);
            if (MODE == 0) {
                float s = nmv[rr];
                v.x *= s; v.y *= s; v.z *= s; v.w *= s;
            } else {
                v.x = fmaxf(v.x, 0.f); v.y = fmaxf(v.y, 0.f);
                v.z = fmaxf(v.z, 0.f); v.w = fmaxf(v.w, 0.f);
            }
            int base = r * ASTR + acol;
            uint32_t h01 = pack_bf2(v.x, v.y), h23 = pack_bf2(v.z, v.w);
            uint32_t l01 = pack_bf2_lo(v.x, v.y), l23 = pack_bf2_lo(v.z, v.w);
            STSV2(smem_u32(&sAhi[base]), h01, h23);
            STSV2(smem_u32(&sAlo[base]), l01, l23);
        }
        __syncthreads();

        const unsigned short* bh_base = sBh + b * 4352;
        const unsigned short* bl_base = sBl + b * 4352;
#pragma unroll
        for (int kk = 0; kk < 32; kk += 16) {
            uint32_t ah[4][4], al[4][4], bh[4][2], bl[4][2];
            const int ar = (lane & 7) + ((lane >> 3) & 1) * 8;
            const int ac = kk + (lane >> 4) * 8;
#pragma unroll
            for (int ms = 0; ms < 4; ms++) {
                int r = wm + ms * 16 + ar;
                LDSM4(ah[ms][0], ah[ms][1], ah[ms][2], ah[ms][3],
                      smem_u32(&sAhi[r * ASTR + ac]));
                LDSM4(al[ms][0], al[ms][1], al[ms][2], al[ms][3],
                      smem_u32(&sAlo[r * ASTR + ac]));
            }
            const int brow = kk + (lane & 7) + ((lane >> 3) & 1) * 8;
#pragma unroll
            for (int g = 0; g < 2; g++) {
                int c = wn + g * 16 + (lane >> 4) * 8;
                uint32_t r0, r1, r2, r3;
                LDSM4T(r0, r1, r2, r3, smem_u32(&bh_base[brow * BSTR + c]));
                bh[g * 2][0] = r0; bh[g * 2][1] = r1;
                bh[g * 2 + 1][0] = r2; bh[g * 2 + 1][1] = r3;
                LDSM4T(r0, r1, r2, r3, smem_u32(&bl_base[brow * BSTR + c]));
                bl[g * 2][0] = r0; bl[g * 2][1] = r1;
                bl[g * 2 + 1][0] = r2; bl[g * 2 + 1][1] = r3;
            }
#pragma unroll
            for (int ms = 0; ms < 4; ms++)
#pragma unroll
                for (int ns = 0; ns < 4; ns++) {
                    mma_bf16(acc[ms][ns], ah[ms], bh[ns]);
                    mma_bf16(acc[ms][ns], ah[ms], bl[ns]);
                    mma_bf16(acc[ms][ns], al[ms], bh[ns]);
                }
        }
    }

#pragma unroll
    for (int ms = 0; ms < 4; ms++) {
#pragma unroll
        for (int ns = 0; ns < 4; ns++) {
            int row = bm + wm + ms * 16 + (lane >> 2);
            int col = bn + wn + ns * 8 + (lane & 3) * 2;
            if (row < M) {
                float2 o = make_float2(acc[ms][ns][0], acc[ms][ns][1]);
                *(float2*)(C + (size_t)row * 256 + col) = o;
            }
            if (row + 8 < M) {
                float2 o = make_float2(acc[ms][ns][2], acc[ms][ns][3]);
                *(float2*)(C + (size_t)(row + 8) * 256 + col) = o;
            }
        }
    }
}

// ---- merged 3-projection launch: z picks fully-specialized body --------------
__global__ void __launch_bounds__(256, 2)
gemm3_mma(const float* __restrict__ A0, const float* __restrict__ A1,
          const float* __restrict__ A2, const float* __restrict__ nm,
          const unsigned short* __restrict__ Wh, const unsigned short* __restrict__ Wl,
          float* __restrict__ C0, float* __restrict__ C1, float* __restrict__ C2)
{
    extern __shared__ __align__(16) char dsm[];
    if (blockIdx.z == 0)
        gemm_body<0>(dsm, A0, nm, Wh + 0 * 65536, Wl + 0 * 65536, C0, N_);
    else if (blockIdx.z == 1)
        gemm_body<0>(dsm, A1, nm, Wh + 1 * 65536, Wl + 1 * 65536, C1, N_);
    else
        gemm_body<1>(dsm, A2, nm, Wh + 2 * 65536, Wl + 2 * 65536, C2, N_);
}

// ====== GEMM (pre-split A): all operands staged by raw cp.async, no split ====
#define GEMMP_SMEM 75776

__global__ void __launch_bounds__(256, 2)
gemm_pre(const unsigned short* __restrict__ Ah, const unsigned short* __restrict__ Al,
         const unsigned short* __restrict__ Bhi, const unsigned short* __restrict__ Blo,
         float* __restrict__ C, int M)
{
    extern __shared__ __align__(16) char dsm[];
    unsigned short* sAh = (unsigned short*)dsm;                  // [2][5120]
    unsigned short* sAl = (unsigned short*)(dsm + 20480);        // [2][5120]
    unsigned short* sBh = (unsigned short*)(dsm + 40960);        // [2][4352]
    unsigned short* sBl = (unsigned short*)(dsm + 58368);        // [2][4352]

    constexpr int ASTR = 40;
    constexpr int BSTR = 136;
    const int tid = threadIdx.x;
    const int lane = tid & 31;
    const int warp = tid >> 5;
    const int wm = (warp & 1) * 64;
    const int wn = (warp >> 1) * 32;
    const int bm = blockIdx.x * 128;
    const int bn = blockIdx.y * 128;

    float acc[4][4][4];
#pragma unroll
    for (int i = 0; i < 4; i++)
#pragma unroll
        for (int j = 0; j < 4; j++)
#pragma unroll
            for (int r = 0; r < 4; r++) acc[i][j][r] = 0.0f;

    auto issue = [&](int kc, int b) {
        int k0 = kc * 32;
#pragma unroll
        for (int j = 0; j < 2; j++) {
            int idx = tid + j * 256;
            int r = idx >> 2;
            int c8 = (idx & 3) << 3;
            int n = (bm + r < M) ? 16 : 0;
            CP_ASYNC16_Z(smem_u32(&sAh[b * 5120 + r * ASTR + c8]),
                         Ah + (size_t)(bm + r) * 256 + k0 + c8, n);
            CP_ASYNC16_Z(smem_u32(&sAl[b * 5120 + r * ASTR + c8]),
                         Al + (size_t)(bm + r) * 256 + k0 + c8, n);
            int rb = idx >> 4;
            int cb = (idx & 15) << 3;
            CP_ASYNC16(smem_u32(&sBh[b * 4352 + rb * BSTR + cb]),
                       Bhi + (size_t)(k0 + rb) * 256 + bn + cb);
            CP_ASYNC16(smem_u32(&sBl[b * 4352 + rb * BSTR + cb]),
                       Blo + (size_t)(k0 + rb) * 256 + bn + cb);
        }
        CP_COMMIT();
    };

    issue(0, 0);
    issue(1, 1);

#pragma unroll 1
    for (int kc = 0; kc < 8; kc++) {
        const int b = kc & 1;
        if (kc < 6) { CP_WAIT_1(); } else { CP_WAIT_ALL(); }
        __syncthreads();

        const unsigned short* ah_base = sAh + b * 5120;
        const unsigned short* al_base = sAl + b * 5120;
        const unsigned short* bh_base = sBh + b * 4352;
        const unsigned short* bl_base = sBl + b * 4352;
#pragma unroll
        for (int kk = 0; kk < 32; kk += 16) {
            uint32_t ah[4][4], al[4][4], bh[4][2], bl[4][2];
            const int ar = (lane & 7) + ((lane >> 3) & 1) * 8;
            const int ac = kk + (lane >> 4) * 8;
#pragma unroll
            for (int ms = 0; ms < 4; ms++) {
                int r = wm + ms * 16 + ar;
                LDSM4(ah[ms][0], ah[ms][1], ah[ms][2], ah[ms][3],
                      smem_u32(&ah_base[r * ASTR + ac]));
                LDSM4(al[ms][0], al[ms][1], al[ms][2], al[ms][3],
                      smem_u32(&al_base[r * ASTR + ac]));
            }
            const int brow = kk + (lane & 7) + ((lane >> 3) & 1) * 8;
#pragma unroll
            for (int g = 0; g < 2; g++) {
                int c = wn + g * 16 + (lane >> 4) * 8;
                uint32_t r0, r1, r2, r3;
                LDSM4T(r0, r1, r2, r3, smem_u32(&bh_base[brow * BSTR + c]));
                bh[g * 2][0] = r0; bh[g * 2][1] = r1;
                bh[g * 2 + 1][0] = r2; bh[g * 2 + 1][1] = r3;
                LDSM4T(r0, r1, r2, r3, smem_u32(&bl_base[brow * BSTR + c]));
                bl[g * 2][0] = r0; bl[g * 2][1] = r1;
                bl[g * 2 + 1][0] = r2; bl[g * 2 + 1][1] = r3;
            }
#pragma unroll
            for (int ms = 0; ms < 4; ms++)
#pragma unroll
                for (int ns = 0; ns < 4; ns++) {
                    mma_bf16(acc[ms][ns], ah[ms], bh[ns]);
                    mma_bf16(acc[ms][ns], ah[ms], bl[ns]);
                    mma_bf16(acc[ms][ns], al[ms], bh[ns]);
                }
        }
        __syncthreads();
        if (kc < 6) issue(kc + 2, b);
    }

#pragma unroll
    for (int ms = 0; ms < 4; ms++) {
#pragma unroll
        for (int ns = 0; ns < 4; ns++) {
            int row = bm + wm + ms * 16 + (lane >> 2);
            int col = bn + wn + ns * 8 + (lane & 3) * 2;
            if (row < M) {
                float2 o = make_float2(acc[ms][ns][0], acc[ms][ns][1]);
                *(float2*)(C + (size_t)row * 256 + col) = o;
            }
            if (row + 8 < M) {
                float2 o = make_float2(acc[ms][ns][2], acc[ms][ns][3]);
                *(float2*)(C + (size_t)(row + 8) * 256 + col) = o;
            }
        }
    }
}

// ---------- warp-per-node fused GAT; writes PRE-SPLIT bf16 hi/lo --------------
template <int RELU>
__global__ void __launch_bounds__(256)
node_gat_kernel(const int* __restrict__ src, const float* __restrict__ emask,
                const float* __restrict__ hs, const float* __restrict__ hd,
                const float* __restrict__ a,
                unsigned short* __restrict__ hh, unsigned short* __restrict__ hl)
{
    int n = (blockIdx.x * blockDim.x + threadIdx.x) >> 5;
    int lane = threadIdx.x & 31;
    if (n >= N_) return;

    const float4* hdp = (const float4*)(hd + (size_t)n * 256) + lane * 2;
    float4 d0 = __ldg(hdp), d1 = __ldg(hdp + 1);
    const float4* ap = (const float4*)a + lane * 2;
    float4 a0 = __ldg(ap), a1v = __ldg(ap + 1);

    float acc[8];
#pragma unroll
    for (int i = 0; i < 8; i++) acc[i] = 0.0f;
    float den = 0.0f;

    int beg = __ldg(&g_rowptr[n]);
    int end = __ldg(&g_cursor[n]);

    float4 n0, n1;
    float emN = 0.0f;
    if (beg < end) {
        int e = __ldg(&g_eid[beg]);
        int s = __ldg(&src[e]);
        emN = __ldg(&emask[e]);
        const float4* hsp = (const float4*)(hs + (size_t)s * 256) + lane * 2;
        n0 = __ldg(hsp); n1 = __ldg(hsp + 1);
    }

    for (int i = beg; i < end; i++) {
        float4 s0 = n0, s1 = n1;
        float em = emN;
        if (i + 1 < end) {
            int e = __ldg(&g_eid[i + 1]);
            int s = __ldg(&src[e]);
            emN = __ldg(&emask[e]);
            const float4* hsp = (const float4*)(hs + (size_t)s * 256) + lane * 2;
            n0 = __ldg(hsp); n1 = __ldg(hsp + 1);
        }

        float v, part = 0.0f;
        v = s0.x + d0.x; v = v > 0.f ? v : 0.2f * v; part = fmaf(a0.x, v, part);
        v = s0.y + d0.y; v = v > 0.f ? v : 0.2f * v; part = fmaf(a0.y, v, part);
        v = s0.z + d0.z; v = v > 0.f ? v : 0.2f * v; part = fmaf(a0.z, v, part);
        v = s0.w + d0.w; v = v > 0.f ? v : 0.2f * v; part = fmaf(a0.w, v, part);
        v = s1.x + d1.x; v = v > 0.f ? v : 0.2f * v; part = fmaf(a1v.x, v, part);
        v = s1.y + d1.y; v = v > 0.f ? v : 0.2f * v; part = fmaf(a1v.y, v, part);
        v = s1.z + d1.z; v = v > 0.f ? v : 0.2f * v; part = fmaf(a1v.z, v, part);
        v = s1.w + d1.w; v = v > 0.f ? v : 0.2f * v; part = fmaf(a1v.w, v, part);

        part += __shfl_xor_sync(0xffffffffu, part, 1);
        part += __shfl_xor_sync(0xffffffffu, part, 2);
        part += __shfl_xor_sync(0xffffffffu, part, 4);

        float p = expf(part);
        den += p;
        float w = p * em;
        acc[0] = fmaf(w, s0.x, acc[0]); acc[1] = fmaf(w, s0.y, acc[1]);
        acc[2] = fmaf(w, s0.z, acc[2]); acc[3] = fmaf(w, s0.w, acc[3]);
        acc[4] = fmaf(w, s1.x, acc[4]); acc[5] = fmaf(w, s1.y, acc[5]);
        acc[6] = fmaf(w, s1.z, acc[6]); acc[7] = fmaf(w, s1.w, acc[7]);
    }

    float inv = 1.0f / (den + 1e-16f);
#pragma unroll
    for (int i = 0; i < 8; i++) {
        acc[i] *= inv;
        if (RELU) acc[i] = fmaxf(acc[i], 0.0f);
    }
    size_t off = (size_t)n * 256 + lane * 8;
    uint4 oh, ol;
    oh.x = pack_bf2(acc[0], acc[1]); oh.y = pack_bf2(acc[2], acc[3]);
    oh.z = pack_bf2(acc[4], acc[5]); oh.w = pack_bf2(acc[6], acc[7]);
    ol.x = pack_bf2_lo(acc[0], acc[1]); ol.y = pack_bf2_lo(acc[2], acc[3]);
    ol.z = pack_bf2_lo(acc[4], acc[5]); ol.w = pack_bf2_lo(acc[6], acc[7]);
    *(uint4*)(hh + off) = oh;
    *(uint4*)(hl + off) = ol;
}

// ---------------- MMA pool: pre-split X -> scores -> softmax -> S^T @ X ------
#define XSTR 264
#define WSTR 72
#define POOL_SMEM (2 * 128 * XSTR * 2 + 2 * 256 * WSTR * 2)

__global__ void __launch_bounds__(256)
pool_mma(const unsigned short* __restrict__ Xhg, const unsigned short* __restrict__ Xlg,
         const float* __restrict__ Wa)
{
    extern __shared__ __align__(16) char smem[];
    unsigned short* Xh = (unsigned short*)smem;
    unsigned short* Xl = Xh + 128 * XSTR;
    unsigned short* Wh = Xl + 128 * XSTR;
    unsigned short* Wl = Wh + 256 * WSTR;
    unsigned short* Sh = Wh;
    unsigned short* Sl = Wl;

    const int tid = threadIdx.x;
    const int lane = tid & 31;
    const int warp = tid >> 5;
    const int row0 = blockIdx.x * 128;

#pragma unroll
    for (int j = 0; j < 16; j++) {
        int idx = tid + j * 256;
        int r = idx >> 5;
        int c8 = (idx & 31) << 3;
        int grow = row0 + r;
        int n = (grow < N_) ? 16 : 0;
        CP_ASYNC16_Z(smem_u32(&Xh[r * XSTR + c8]), Xhg + (size_t)grow * 256 + c8, n);
        CP_ASYNC16_Z(smem_u32(&Xl[r * XSTR + c8]), Xlg + (size_t)grow * 256 + c8, n);
    }
    CP_COMMIT();
#pragma unroll
    for (int j = 0; j < 16; j++) {
        int idx = tid + j * 256;
        int r = idx >> 4;
        int c4 = (idx & 15) << 2;
        float4 v = *(const float4*)(Wa + (size_t)r * 64 + c4);
        int base = r * WSTR + c4;
        uint32_t h01 = pack_bf2(v.x, v.y), h23 = pack_bf2(v.z, v.w);
        uint32_t l01 = pack_bf2_lo(v.x, v.y), l23 = pack_bf2_lo(v.z, v.w);
        STSV2(smem_u32(&Wh[base]), h01, h23);
        STSV2(smem_u32(&Wl[base]), l01, l23);
    }
    CP_WAIT_ALL();
    __syncthreads();

    float sc[8][4];
#pragma unroll
    for (int i = 0; i < 8; i++)
#pragma unroll
        for (int r = 0; r < 4; r++) sc[i][r] = 0.0f;

    const int arow = (lane & 7) + ((lane >> 3) & 1) * 8;
#pragma unroll 1
    for (int k = 0; k < 256; k += 16) {
        uint32_t ah[4], al[4];
        int rbase = (warp * 16 + arow) * XSTR + k + (lane >> 4) * 8;
        LDSM4(ah[0], ah[1], ah[2], ah[3], smem_u32(&Xh[rbase]));
        LDSM4(al[0], al[1], al[2], al[3], smem_u32(&Xl[rbase]));
        uint32_t bh[8][2], bl[8][2];
        int brow = k + (lane & 7) + ((lane >> 3) & 1) * 8;
#pragma unroll
        for (int g = 0; g < 4; g++) {
            int c = g * 16 + (lane >> 4) * 8;
            uint32_t r0, r1, r2, r3;
            LDSM4T(r0, r1, r2, r3, smem_u32(&Wh[brow * WSTR + c]));
            bh[g * 2][0] = r0; bh[g * 2][1] = r1;
            bh[g * 2 + 1][0] = r2; bh[g * 2 + 1][1] = r3;
            LDSM4T(r0, r1, r2, r3, smem_u32(&Wl[brow * WSTR + c]));
            bl[g * 2][0] = r0; bl[g * 2][1] = r1;
            bl[g * 2 + 1][0] = r2; bl[g * 2 + 1][1] = r3;
        }
#pragma unroll
        for (int ns = 0; ns < 8; ns++) {
            mma_bf16(sc[ns], ah, bh[ns]);
            mma_bf16(sc[ns], ah, bl[ns]);
            mma_bf16(sc[ns], al, bh[ns]);
        }
    }

    float mA = -1e30f, mB = -1e30f;
#pragma unroll
    for (int ns = 0; ns < 8; ns++) {
        mA = fmaxf(mA, fmaxf(sc[ns][0], sc[ns][1]));
        mB = fmaxf(mB, fmaxf(sc[ns][2], sc[ns][3]));
    }
    mA = fmaxf(mA, __shfl_xor_sync(0xffffffffu, mA, 1));
    mA = fmaxf(mA, __shfl_xor_sync(0xffffffffu, mA, 2));
    mB = fmaxf(mB, __shfl_xor_sync(0xffffffffu, mB, 1));
    mB = fmaxf(mB, __shfl_xor_sync(0xffffffffu, mB, 2));
    float sumA = 0.0f, sumB = 0.0f;
#pragma unroll
    for (int ns = 0; ns < 8; ns++) {
        sc[ns][0] = expf(sc[ns][0] - mA); sc[ns][1] = expf(sc[ns][1] - mA);
        sc[ns][2] = expf(sc[ns][2] - mB); sc[ns][3] = expf(sc[ns][3] - mB);
        sumA += sc[ns][0] + sc[ns][1];
        sumB += sc[ns][2] + sc[ns][3];
    }
    sumA += __shfl_xor_sync(0xffffffffu, sumA, 1);
    sumA += __shfl_xor_sync(0xffffffffu, sumA, 2);
    sumB += __shfl_xor_sync(0xffffffffu, sumB, 1);
    sumB += __shfl_xor_sync(0xffffffffu, sumB, 2);
    float invA = 1.0f / sumA, invB = 1.0f / sumB;

    __syncthreads();

    {
        int rA = warp * 16 + (lane >> 2);
        int rB = rA + 8;
        int colb = (lane & 3) * 2;
#pragma unroll
        for (int ns = 0; ns < 8; ns++) {
            int col = ns * 8 + colb;
            float a0 = sc[ns][0] * invA, a1 = sc[ns][1] * invA;
            float b0 = sc[ns][2] * invB, b1 = sc[ns][3] * invB;
            *(uint32_t*)&Sh[rA * WSTR + col] = pack_bf2(a0, a1);
            *(uint32_t*)&Sl[rA * WSTR + col] = pack_bf2_lo(a0, a1);
            *(uint32_t*)&Sh[rB * WSTR + col] = pack_bf2(b0, b1);
            *(uint32_t*)&Sl[rB * WSTR + col] = pack_bf2_lo(b0, b1);
        }
    }
    __syncthreads();

    float pc[4][4][4];
#pragma unroll
    for (int i = 0; i < 4; i++)
#pragma unroll
        for (int j = 0; j < 4; j++)
#pragma unroll
            for (int r = 0; r < 4; r++) pc[i][j][r] = 0.0f;

    const int nw = warp * 32;
#pragma unroll 1
    for (int kk = 0; kk < 128; kk += 16) {
        uint32_t sah[4][4], sal[4][4];
        int srow = kk + ((lane >> 4) & 1) * 8 + (lane & 7);
        int scoff = ((lane >> 3) & 1) * 8;
#pragma unroll
        for (int mt = 0; mt < 4; mt++) {
            int sc2 = mt * 16 + scoff;
            LDSM4T(sah[mt][0], sah[mt][1], sah[mt][2], sah[mt][3],
                   smem_u32(&Sh[srow * WSTR + sc2]));
            LDSM4T(sal[mt][0], sal[mt][1], sal[mt][2], sal[mt][3],
                   smem_u32(&Sl[srow * WSTR + sc2]));
        }
        uint32_t xbh[4][2], xbl[4][2];
        int brow = kk + (lane & 7) + ((lane >> 3) & 1) * 8;
#pragma unroll
        for (int g = 0; g < 2; g++) {
            int c = nw + g * 16 + (lane >> 4) * 8;
            uint32_t r0, r1, r2, r3;
            LDSM4T(r0, r1, r2, r3, smem_u32(&Xh[brow * XSTR + c]));
            xbh[g * 2][0] = r0; xbh[g * 2][1] = r1;
            xbh[g * 2 + 1][0] = r2; xbh[g * 2 + 1][1] = r3;
            LDSM4T(r0, r1, r2, r3, smem_u32(&Xl[brow * XSTR + c]));
            xbl[g * 2][0] = r0; xbl[g * 2][1] = r1;
            xbl[g * 2 + 1][0] = r2; xbl[g * 2 + 1][1] = r3;
        }
#pragma unroll
        for (int mt = 0; mt < 4; mt++)
#pragma unroll
            for (int ns = 0; ns < 4; ns++) {
                mma_bf16(pc[mt][ns], sah[mt], xbh[ns]);
                mma_bf16(pc[mt][ns], sah[mt], xbl[ns]);
                mma_bf16(pc[mt][ns], sal[mt], xbh[ns]);
            }
    }

#pragma unroll
    for (int mt = 0; mt < 4; mt++)
#pragma unroll
        for (int ns = 0; ns < 4; ns++) {
            int kidx = mt * 16 + (lane >> 2);
            int col = nw + ns * 8 + (lane & 3) * 2;
            redAddV2(&g_pool[(size_t)kidx * 256 + col], pc[mt][ns][0], pc[mt][ns][1]);
            redAddV2(&g_pool[(size_t)(kidx + 8) * 256 + col], pc[mt][ns][2], pc[mt][ns][3]);
        }
}

// ---------------- final classifier -------------------------------------------
__global__ void final_kernel(const float* __restrict__ Wcls, const float* __restrict__ bcls,
                             float* __restrict__ out)
{
    int k = blockIdx.x;
    int lane = threadIdx.x;
    float s = 0.0f;
    for (int d = lane; d < 256; d += 32) s += g_pool[(size_t)k * 256 + d] * Wcls[d];
#pragma unroll
    for (int o = 16; o; o >>= 1) s += __shfl_xor_sync(0xffffffffu, s, o);
    if (lane == 0) {
        float extra = 0.0f;
#pragma unroll
        for (int t = 0; t < T_; t++) extra += (g_esum[t] * (1.0f / E_)) * Wcls[256 + t];
        float z = s + extra + bcls[0];
        out[k] = 1.0f / (1.0f + expf(-z));
    }
}

// ---------------- launch -------------------------------------------------------
extern "C" void kernel_launch(void* const* d_in, const int* in_sizes, int n_in,
                              void* d_out, int out_size)
{
    const float* x_pkg = (const float*)d_in[0];
    const float* x_dst = (const float*)d_in[1];
    const int*   eidx  = (const int*)d_in[2];
    const float* eattr = (const float*)d_in[3];
    const float* nmask = (const float*)d_in[4];
    const float* emask = (const float*)d_in[5];
    const float* W1s   = (const float*)d_in[6];
    const float* W1d   = (const float*)d_in[7];
    const float* a1    = (const float*)d_in[8];
    const float* W2s   = (const float*)d_in[9];
    const float* W2d   = (const float*)d_in[10];
    const float* a2    = (const float*)d_in[11];
    const float* Was   = (const float*)d_in[12];
    const float* Wcl   = (const float*)d_in[13];
    const float* bcl   = (const float*)d_in[14];
    float* out = (float*)d_out;

    const int tsel = T_ - 1;
    const int* src5 = eidx + (size_t)tsel * 2 * E_;
    const int* dst5 = src5 + E_;
    const float* x_dst5 = x_dst + (size_t)tsel * N_ * D_;
    const float* W1s5 = W1s + (size_t)tsel * D_ * 256;
    const float* W1d5 = W1d + (size_t)tsel * D_ * 256;
    const float* a1_5 = a1 + (size_t)tsel * 256;
    const float* W2s5 = W2s + (size_t)tsel * D_ * 256;
    const float* W2d5 = W2d + (size_t)tsel * D_ * 256;
    const float* a2_5 = a2 + (size_t)tsel * 256;

    float *hs1, *hd1, *hs2, *hd2;
    unsigned short *whi, *wlo, *h1h, *h1l, *h2h, *h2l;
    cudaGetSymbolAddress((void**)&hs1, g_hs1);
    cudaGetSymbolAddress((void**)&hd1, g_hd1);
    cudaGetSymbolAddress((void**)&hs2, g_hs2);
    cudaGetSymbolAddress((void**)&hd2, g_hd2);
    cudaGetSymbolAddress((void**)&whi, g_Whi);
    cudaGetSymbolAddress((void**)&wlo, g_Wlo);
    cudaGetSymbolAddress((void**)&h1h, g_h1h);
    cudaGetSymbolAddress((void**)&h1l, g_h1l);
    cudaGetSymbolAddress((void**)&h2h, g_h2h);
    cudaGetSymbolAddress((void**)&h2l, g_h2l);

    cudaFuncSetAttribute(pool_mma, cudaFuncAttributeMaxDynamicSharedMemorySize, POOL_SMEM);
    cudaFuncSetAttribute(gemm3_mma, cudaFuncAttributeMaxDynamicSharedMemorySize, GEMM_SMEM);
    cudaFuncSetAttribute(gemm_pre, cudaFuncAttributeMaxDynamicSharedMemorySize, GEMMP_SMEM);

    const int ngrid = (N_ * 32 + 255) / 256;

    // ONE launch: init + weight split + edge sums + full CSR build
    mega_prep_kernel<<<MGRID, 256>>>(dst5, eattr, W1s5, W1d5, W2s5, W2d5);

    // 3 independent projections in ONE launch; per-z fully templated dispatch
    gemm3_mma<<<dim3(391, 2, 3), 256, GEMM_SMEM>>>(x_pkg, x_dst5, x_pkg, nmask,
                                                   whi, wlo, hs1, hd1, hs2);

    node_gat_kernel<1><<<ngrid, 256>>>(src5, emask, hs1, hd1, a1_5, h1h, h1l);

    gemm_pre<<<dim3(391, 2), 256, GEMMP_SMEM>>>(h1h, h1l, whi + 3 * 65536, wlo + 3 * 65536, hd2, N_);

    node_gat_kernel<0><<<ngrid, 256>>>(src5, emask, hs2, hd2, a2_5, h2h, h2l);

    pool_mma<<<391, 256, POOL_SMEM>>>(h2h, h2l, Was);
    final_kernel<<<K_, 32>>>(Wcl, bcl, out);
}